// round 1
// baseline (speedup 1.0000x reference)
#include <cuda_runtime.h>
#include <math.h>

#define BB   64
#define LL   4096
#define RC   64
#define SC   128
#define NBLK 30
#define PITCH 129   // 128 + 1 to avoid smem bank conflicts on [c][pos] layout

// Static device scratch (allocation-free contract)
__device__ float g_h0[(size_t)BB * LL * RC];        // 64 MB
__device__ float g_h1[(size_t)BB * LL * RC];        // 64 MB
__device__ float g_skip[(size_t)BB * LL * SC];      // 128 MB
__device__ float g_partial[(size_t)BB * 32 * SC];   // per-tile column sums

// ---------------------------------------------------------------------------
// Input projection: h[b,l,oc] = b_in[oc] + sum_c w_in[oc,c] * x[b,c,l]
// ---------------------------------------------------------------------------
__global__ __launch_bounds__(256) void proj_kernel(
    const float* __restrict__ x, const float* __restrict__ w_in,
    const float* __restrict__ b_in, float* __restrict__ h)
{
    int idx = blockIdx.x * 256 + threadIdx.x;     // = ((b*L)+l)*64 + oc
    int oc = idx & 63;
    int l  = (idx >> 6) & (LL - 1);
    int b  = idx >> 18;
    float acc = b_in[oc];
#pragma unroll
    for (int c = 0; c < 8; ++c)
        acc += w_in[oc * 8 + c] * x[((size_t)(b * 8 + c)) * LL + l];
    h[(size_t)idx] = acc;
}

// ---------------------------------------------------------------------------
// One WaveNet block: dilated conv (K=2) -> tanh*sigmoid gate -> res (+h) and
// skip (+=) projections. CTA = 128 positions of one batch. 256 threads.
// ---------------------------------------------------------------------------
__global__ __launch_bounds__(256) void block_kernel(
    const float* __restrict__ h_in, float* __restrict__ h_out,
    float* __restrict__ skip,
    const float* __restrict__ wd, const float* __restrict__ bd,
    const float* __restrict__ wr, const float* __restrict__ br,
    const float* __restrict__ ws, const float* __restrict__ bs,
    int d, int first)
{
    extern __shared__ float sm[];
    float* s_cur = sm;                    // [64][PITCH]  h[l]
    float* s_del = s_cur + 64 * PITCH;    // [64][PITCH]  h[l-d]; reused as s-half
    float* s_g   = s_del + 64 * PITCH;    // [64][PITCH]  t-half, then gated
    float* s_wd  = s_g   + 64 * PITCH;    // [64][2][128] conv weights (k-major)
    float* s_wr  = s_wd + 16384;          // [64][64]     res weights (c-major)
    float* s_ws  = s_wr + 4096;           // [64][128]    skip weights (c-major)

    const int tid = threadIdx.x;
    const int b   = blockIdx.y;
    const int l0  = blockIdx.x * 128;

    // ---- stage activations ----
    {
        int c  = tid & 63;
        int p0 = tid >> 6;
        const float* hb = h_in + (size_t)b * LL * 64;
#pragma unroll 4
        for (int p = p0; p < 128; p += 4) {
            int l = l0 + p;
            s_cur[c * PITCH + p] = hb[(size_t)l * 64 + c];
            int ld = l - d;
            s_del[c * PITCH + p] = (ld >= 0) ? hb[(size_t)ld * 64 + c] : 0.f;
        }
    }
    // ---- stage weights (transposed to k-major / c-major) ----
    for (int e = tid; e < 16384; e += 256) {        // wd[(o*64+c)*2+k] -> s_wd[(c*2+k)*128+o]
        int o = e >> 7; int r = e & 127;
        s_wd[r * 128 + o] = wd[e];
    }
    for (int e = tid; e < 4096; e += 256) {         // wr[j*64+c] -> s_wr[c*64+j]
        int j = e >> 6, c = e & 63;
        s_wr[c * 64 + j] = wr[e];
    }
    for (int e = tid; e < 8192; e += 256) {         // ws[s*64+c] -> s_ws[c*128+s]
        int s = e >> 6, c = e & 63;
        s_ws[c * 128 + s] = ws[e];
    }
    __syncthreads();

    const int pt = tid >> 4;     // 16 position tiles of 8
    const int ot = tid & 15;     // 16 output tiles of 8
    const int pb = pt * 8;
    const int ob = ot * 8;

    // ---- conv GEMM: 128 pos x 128 out, K = 64 channels x 2 taps ----
    float acc[8][8];
#pragma unroll
    for (int p = 0; p < 8; p++)
#pragma unroll
        for (int o = 0; o < 8; o++) acc[p][o] = 0.f;

#pragma unroll 4
    for (int k = 0; k < 64; ++k) {
        float xc[8], xd[8], w0[8], w1[8];
        const float* wp = s_wd + k * 256;
#pragma unroll
        for (int o = 0; o < 8; o++) { w0[o] = wp[ob + o]; w1[o] = wp[128 + ob + o]; }
#pragma unroll
        for (int p = 0; p < 8; p++) {
            xc[p] = s_cur[k * PITCH + pb + p];
            xd[p] = s_del[k * PITCH + pb + p];
        }
#pragma unroll
        for (int p = 0; p < 8; p++)
#pragma unroll
            for (int o = 0; o < 8; o++)
                acc[p][o] += xd[p] * w0[o] + xc[p] * w1[o];
    }
    __syncthreads();   // everyone done reading s_del -> safe to reuse as s-half

    // ---- scatter t-half into s_g, s-half into s_del (with conv bias) ----
    {
        float* dst = (ob < 64) ? s_g : s_del;
        int oo = ob & 63;
#pragma unroll
        for (int o = 0; o < 8; o++) {
            float bias = bd[ob + o];
#pragma unroll
            for (int p = 0; p < 8; p++)
                dst[(oo + o) * PITCH + pb + p] = acc[p][o] + bias;
        }
    }
    __syncthreads();

    // ---- gated = tanh(t) * sigmoid(s), written back into s_g ----
    {
        int c  = tid & 63;
        int p0 = (tid >> 6) * 32;
        for (int p = p0; p < p0 + 32; ++p) {
            float t = s_g[c * PITCH + p];
            float s = s_del[c * PITCH + p];
            s_g[c * PITCH + p] = tanhf(t) * (1.f / (1.f + expf(-s)));
        }
    }
    __syncthreads();

    // ---- res GEMM (64 out) + residual + bias -> h_out ----
    {
        const int j0 = ot * 4;
        float racc[8][4];
#pragma unroll
        for (int p = 0; p < 8; p++)
#pragma unroll
            for (int j = 0; j < 4; j++) racc[p][j] = 0.f;
#pragma unroll 4
        for (int k = 0; k < 64; k++) {
            float g[8], w[4];
#pragma unroll
            for (int p = 0; p < 8; p++) g[p] = s_g[k * PITCH + pb + p];
#pragma unroll
            for (int j = 0; j < 4; j++) w[j] = s_wr[k * 64 + j0 + j];
#pragma unroll
            for (int p = 0; p < 8; p++)
#pragma unroll
                for (int j = 0; j < 4; j++) racc[p][j] += g[p] * w[j];
        }
        float bj[4];
#pragma unroll
        for (int j = 0; j < 4; j++) bj[j] = br[j0 + j];
#pragma unroll
        for (int p = 0; p < 8; p++) {
            int l = l0 + pb + p;
            float4 v;
            v.x = racc[p][0] + bj[0] + s_cur[(j0 + 0) * PITCH + pb + p];
            v.y = racc[p][1] + bj[1] + s_cur[(j0 + 1) * PITCH + pb + p];
            v.z = racc[p][2] + bj[2] + s_cur[(j0 + 2) * PITCH + pb + p];
            v.w = racc[p][3] + bj[3] + s_cur[(j0 + 3) * PITCH + pb + p];
            *reinterpret_cast<float4*>(&h_out[((size_t)b * LL + l) * 64 + j0]) = v;
        }
    }

    // ---- skip GEMM (128 out), global read-modify-write ----
    {
        const int s0 = ob;
        float sacc[8][8];
#pragma unroll
        for (int p = 0; p < 8; p++) {
            size_t base = ((size_t)b * LL + l0 + pb + p) * 128 + s0;
            if (first) {
#pragma unroll
                for (int o = 0; o < 8; o++) sacc[p][o] = bs[s0 + o];
            } else {
                float4 a  = *reinterpret_cast<const float4*>(&skip[base]);
                float4 a2 = *reinterpret_cast<const float4*>(&skip[base + 4]);
                sacc[p][0] = a.x  + bs[s0 + 0]; sacc[p][1] = a.y  + bs[s0 + 1];
                sacc[p][2] = a.z  + bs[s0 + 2]; sacc[p][3] = a.w  + bs[s0 + 3];
                sacc[p][4] = a2.x + bs[s0 + 4]; sacc[p][5] = a2.y + bs[s0 + 5];
                sacc[p][6] = a2.z + bs[s0 + 6]; sacc[p][7] = a2.w + bs[s0 + 7];
            }
        }
#pragma unroll 4
        for (int k = 0; k < 64; k++) {
            float g[8], w[8];
#pragma unroll
            for (int p = 0; p < 8; p++) g[p] = s_g[k * PITCH + pb + p];
#pragma unroll
            for (int o = 0; o < 8; o++) w[o] = s_ws[k * 128 + s0 + o];
#pragma unroll
            for (int p = 0; p < 8; p++)
#pragma unroll
                for (int o = 0; o < 8; o++) sacc[p][o] += g[p] * w[o];
        }
#pragma unroll
        for (int p = 0; p < 8; p++) {
            size_t base = ((size_t)b * LL + l0 + pb + p) * 128 + s0;
            float4 v;  v.x  = sacc[p][0]; v.y  = sacc[p][1]; v.z  = sacc[p][2]; v.w  = sacc[p][3];
            float4 v2; v2.x = sacc[p][4]; v2.y = sacc[p][5]; v2.z = sacc[p][6]; v2.w = sacc[p][7];
            *reinterpret_cast<float4*>(&skip[base])     = v;
            *reinterpret_cast<float4*>(&skip[base + 4]) = v2;
        }
    }
}

// ---------------------------------------------------------------------------
// Post: relu(skip) -> out1 -> relu -> out2 -> per-tile column sums
// ---------------------------------------------------------------------------
__global__ __launch_bounds__(256) void post_kernel(
    const float* __restrict__ skip,
    const float* __restrict__ w1g, const float* __restrict__ b1,
    const float* __restrict__ w2g, const float* __restrict__ b2,
    float* __restrict__ partial)
{
    extern __shared__ float sm[];
    float* s_r0  = sm;                     // [128][PITCH]
    float* s_t1  = s_r0 + 128 * PITCH;     // [128][PITCH]
    float* s_w   = s_t1 + 128 * PITCH;     // [128][128]
    float* s_red = s_w + 16384;            // [16][128]

    const int tid = threadIdx.x;
    const int b   = blockIdx.y;
    const int l0  = blockIdx.x * 128;

    {
        int c  = tid & 127;
        int p0 = tid >> 7;
        for (int p = p0; p < 128; p += 2) {
            float v = skip[((size_t)b * LL + l0 + p) * 128 + c];
            s_r0[c * PITCH + p] = fmaxf(v, 0.f);
        }
    }
    for (int e = tid; e < 16384; e += 256) {    // w1[o*128+c] -> s_w[c*128+o]
        int o = e >> 7, c = e & 127;
        s_w[c * 128 + o] = w1g[e];
    }
    __syncthreads();

    const int pt = tid >> 4, ot = tid & 15;
    const int pb = pt * 8, ob = ot * 8;

    float acc[8][8];
#pragma unroll
    for (int p = 0; p < 8; p++)
#pragma unroll
        for (int o = 0; o < 8; o++) acc[p][o] = 0.f;
#pragma unroll 4
    for (int k = 0; k < 128; k++) {
        float g[8], w[8];
#pragma unroll
        for (int p = 0; p < 8; p++) g[p] = s_r0[k * PITCH + pb + p];
#pragma unroll
        for (int o = 0; o < 8; o++) w[o] = s_w[k * 128 + ob + o];
#pragma unroll
        for (int p = 0; p < 8; p++)
#pragma unroll
            for (int o = 0; o < 8; o++) acc[p][o] += g[p] * w[o];
    }
    __syncthreads();
#pragma unroll
    for (int o = 0; o < 8; o++) {
        float bias = b1[ob + o];
#pragma unroll
        for (int p = 0; p < 8; p++)
            s_t1[(ob + o) * PITCH + pb + p] = fmaxf(acc[p][o] + bias, 0.f);
    }
    __syncthreads();
    for (int e = tid; e < 16384; e += 256) {    // w2 -> s_w (overwrite)
        int o = e >> 7, c = e & 127;
        s_w[c * 128 + o] = w2g[e];
    }
    __syncthreads();

    float acc2[8][8];
#pragma unroll
    for (int p = 0; p < 8; p++)
#pragma unroll
        for (int o = 0; o < 8; o++) acc2[p][o] = 0.f;
#pragma unroll 4
    for (int k = 0; k < 128; k++) {
        float g[8], w[8];
#pragma unroll
        for (int p = 0; p < 8; p++) g[p] = s_t1[k * PITCH + pb + p];
#pragma unroll
        for (int o = 0; o < 8; o++) w[o] = s_w[k * 128 + ob + o];
#pragma unroll
        for (int p = 0; p < 8; p++)
#pragma unroll
            for (int o = 0; o < 8; o++) acc2[p][o] += g[p] * w[o];
    }
    // deterministic column sums over the 128 positions of this tile
#pragma unroll
    for (int o = 0; o < 8; o++) {
        float s = 0.f;
#pragma unroll
        for (int p = 0; p < 8; p++) s += acc2[p][o];
        s_red[pt * 128 + ob + o] = s;
    }
    __syncthreads();
    if (tid < 128) {
        float sum = 0.f;
        for (int t = 0; t < 16; t++) sum += s_red[t * 128 + tid];
        partial[((size_t)b * 32 + blockIdx.x) * 128 + tid] = sum + 128.f * b2[tid];
    }
}

// ---------------------------------------------------------------------------
// Final: reduce partials -> mean -> fc1 -> fc2 -> fc3. One CTA per batch row.
// ---------------------------------------------------------------------------
__global__ __launch_bounds__(256) void final_kernel(
    const float* __restrict__ partial,
    const float* __restrict__ wf1, const float* __restrict__ bf1,
    const float* __restrict__ wf2, const float* __restrict__ bf2,
    const float* __restrict__ wf3, const float* __restrict__ bf3,
    float* __restrict__ out)
{
    __shared__ float pooled[128];
    __shared__ float z1[256];
    __shared__ float z2[128];
    int b = blockIdx.x, tid = threadIdx.x;
    if (tid < 128) {
        float s = 0.f;
        for (int t = 0; t < 32; t++) s += partial[((size_t)b * 32 + t) * 128 + tid];
        pooled[tid] = s * (1.f / (float)LL);
    }
    __syncthreads();
    {
        float a = bf1[tid];
        for (int c = 0; c < 128; c++) a += wf1[tid * 128 + c] * pooled[c];
        z1[tid] = fmaxf(a, 0.f);
    }
    __syncthreads();
    if (tid < 128) {
        float a = bf2[tid];
        for (int c = 0; c < 256; c++) a += wf2[tid * 256 + c] * z1[c];
        z2[tid] = fmaxf(a, 0.f);
    }
    __syncthreads();
    if (tid < 6) {
        float a = bf3[tid];
        for (int c = 0; c < 128; c++) a += wf3[tid * 128 + c] * z2[c];
        out[b * 6 + tid] = a;
    }
}

// ---------------------------------------------------------------------------
extern "C" void kernel_launch(void* const* d_in, const int* in_sizes, int n_in,
                              void* d_out, int out_size)
{
    const float* x      = (const float*)d_in[0];
    const float* w_in   = (const float*)d_in[1];
    const float* b_in   = (const float*)d_in[2];
    const float* w_dil  = (const float*)d_in[3];
    const float* b_dil  = (const float*)d_in[4];
    const float* w_res  = (const float*)d_in[5];
    const float* b_res  = (const float*)d_in[6];
    const float* w_skip = (const float*)d_in[7];
    const float* b_skip = (const float*)d_in[8];
    const float* w_out1 = (const float*)d_in[9];
    const float* b_out1 = (const float*)d_in[10];
    const float* w_out2 = (const float*)d_in[11];
    const float* b_out2 = (const float*)d_in[12];
    const float* w_fc1  = (const float*)d_in[13];
    const float* b_fc1  = (const float*)d_in[14];
    const float* w_fc2  = (const float*)d_in[15];
    const float* b_fc2  = (const float*)d_in[16];
    const float* w_fc3  = (const float*)d_in[17];
    const float* b_fc3  = (const float*)d_in[18];
    float* out = (float*)d_out;

    float *h0, *h1, *skipb, *partial;
    cudaGetSymbolAddress((void**)&h0,      g_h0);
    cudaGetSymbolAddress((void**)&h1,      g_h1);
    cudaGetSymbolAddress((void**)&skipb,   g_skip);
    cudaGetSymbolAddress((void**)&partial, g_partial);

    const int BLOCK_SMEM = (3 * 64 * PITCH + 16384 + 4096 + 8192) * 4;   // 213,760 B
    const int POST_SMEM  = (2 * 128 * PITCH + 16384 + 2048) * 4;         // 205,824 B
    cudaFuncSetAttribute(block_kernel, cudaFuncAttributeMaxDynamicSharedMemorySize, BLOCK_SMEM);
    cudaFuncSetAttribute(post_kernel,  cudaFuncAttributeMaxDynamicSharedMemorySize, POST_SMEM);

    proj_kernel<<<(BB * LL * 64) / 256, 256>>>(x, w_in, b_in, h0);

    dim3 grid(LL / 128, BB);
    const float* hin = h0;
    float* hout = h1;
    for (int i = 0; i < NBLK; ++i) {
        int d = 1 << (i % 10);
        block_kernel<<<grid, 256, BLOCK_SMEM>>>(
            hin, hout, skipb,
            w_dil + (size_t)i * 128 * 64 * 2, b_dil + i * 128,
            w_res + (size_t)i * 64 * 64,      b_res + i * 64,
            w_skip + (size_t)i * 128 * 64,    b_skip + i * 128,
            d, (i == 0) ? 1 : 0);
        const float* t = hout;
        hout = (float*)hin;
        hin = t;
    }

    post_kernel<<<grid, 256, POST_SMEM>>>(skipb, w_out1, b_out1, w_out2, b_out2, partial);
    final_kernel<<<BB, 256>>>(partial, w_fc1, b_fc1, w_fc2, b_fc2, w_fc3, b_fc3, out);
}